// round 8
// baseline (speedup 1.0000x reference)
#include <cuda_runtime.h>

// pRNN_45492293599807 — only node N-1 is observed by the outputs.
// Live work per batch row: gather 32 values, one 32x32 matvec + one 32-dot.
//
// Shapes: B=1024, I=256, N=2048, D=32, C=32
// Inputs (metadata order):
//   0: x (B,I) f32   1: h0 (B,N,D) f32   2: conv_w (I,) f32   3: conv_b (I,) f32
//   4: W (N,D,C) f32 5: b (N,D) f32      6: W_out (1,C) f32   7: b_out (1,) f32
//   8: idx (N,C) i32 in [0, I+N*D)
// Output: [ out_nodes[:, -1] (B, D) | out2 (B, 1) ] -> B*D + B floats
//
// Design: 1 warp per batch row, 8 warps/block, 128 blocks (single wave, no
// smem, no barriers). Kernel is launch-overhead + latency-chain bound
// (T_ovh ~5000cyc dominates); the only tunable term is the 2-deep dependent
// load chain idx -> gather. The gather is BRANCHLESS: both the x-path loads
// and the h0 load are issued speculatively (clamped addresses) at the same
// dependency level, then selected — no BSSY/BSYNC on the critical path.

#define PB 1024
#define PI 256
#define PN 2048
#define PD 32
#define PC 32

__global__ __launch_bounds__(256, 8)
void prnn_last_node_kernel(const float* __restrict__ x,
                           const float* __restrict__ h0,
                           const float* __restrict__ conv_w,
                           const float* __restrict__ conv_b,
                           const float* __restrict__ W,
                           const float* __restrict__ bias,
                           const float* __restrict__ W_out,
                           const float* __restrict__ b_out,
                           const int*   __restrict__ idx,
                           float* __restrict__ out)
{
    const int tid  = threadIdx.x;
    const int warp = tid >> 5;
    const int lane = tid & 31;
    const int b    = blockIdx.x * 8 + warp;   // one batch row per warp

    // ---- level-0 loads (independent, issued up front) ----
    // idx row N-1: one 128B line, L2-broadcast to every block.
    const int j = __ldg(&idx[(PN - 1) * PC + lane]);

    // W row for this lane: W[N-1, lane, 0..31] — contiguous 128 bytes.
    const float4* wrow4 =
        (const float4*)(W + ((size_t)(PN - 1) * PD + lane) * PC);
    float4 w0 = wrow4[0], w1 = wrow4[1], w2 = wrow4[2], w3 = wrow4[3];
    float4 w4 = wrow4[4], w5 = wrow4[5], w6 = wrow4[6], w7 = wrow4[7];

    const float bl = __ldg(&bias[(PN - 1) * PD + lane]);
    const float wo = __ldg(&W_out[lane]);
    const float bo = __ldg(&b_out[0]);

    // ---- level-1 loads (depend only on j), branchless: issue BOTH paths ----
    const bool in_x = (j < PI);
    const int  jx   = in_x ? j : (PI - 1);        // clamped x-path index
    const int  jh   = in_x ? 0 : (j - PI);        // clamped h0-path index

    const float xv  = x[(size_t)b * PI + jx];
    const float cw  = __ldg(&conv_w[jx]);
    const float cb  = __ldg(&conv_b[jx]);
    const float hv  = h0[(size_t)b * (PN * PD) + jh];   // h0.reshape(B, N*D)

    float gx = fmaf(xv, cw, cb);
    gx = gx > 0.0f ? gx : 0.0f;                   // relu(conv) path
    const float g = in_x ? gx : hv;               // select

    // ---- out_nodes[:, -1]: lane == d; broadcast g[c] via shfl ----
    float wreg[PC] = {
        w0.x, w0.y, w0.z, w0.w,  w1.x, w1.y, w1.z, w1.w,
        w2.x, w2.y, w2.z, w2.w,  w3.x, w3.y, w3.z, w3.w,
        w4.x, w4.y, w4.z, w4.w,  w5.x, w5.y, w5.z, w5.w,
        w6.x, w6.y, w6.z, w6.w,  w7.x, w7.y, w7.z, w7.w
    };

    float acc  = bl;
    float acc2 = g * wo;                  // out2 partial (lane == c)
    #pragma unroll
    for (int c = 0; c < PC; c++) {
        float gc = __shfl_sync(0xffffffffu, g, c);
        acc = fmaf(gc, wreg[c], acc);
    }
    acc = acc > 0.0f ? acc : 0.0f;
    out[(size_t)b * PD + lane] = acc;

    // ---- out2[b]: butterfly reduce of g[c] * W_out[c] ----
    #pragma unroll
    for (int o = 16; o > 0; o >>= 1)
        acc2 += __shfl_xor_sync(0xffffffffu, acc2, o);
    if (lane == 0) {
        float v = acc2 + bo;
        out[PB * PD + b] = v > 0.0f ? v : 0.0f;
    }
}

extern "C" void kernel_launch(void* const* d_in, const int* in_sizes, int n_in,
                              void* d_out, int out_size)
{
    const float* x      = (const float*)d_in[0];
    const float* h0     = (const float*)d_in[1];
    const float* conv_w = (const float*)d_in[2];
    const float* conv_b = (const float*)d_in[3];
    const float* W      = (const float*)d_in[4];
    const float* bias   = (const float*)d_in[5];
    const float* W_out  = (const float*)d_in[6];
    const float* b_out  = (const float*)d_in[7];
    const int*   idx    = (const int*)d_in[8];
    float* out = (float*)d_out;

    // 8 batch rows per block (one per warp), 1024/8 = 128 blocks.
    prnn_last_node_kernel<<<PB / 8, 256>>>(x, h0, conv_w, conv_b, W, bias,
                                           W_out, b_out, idx, out);
}